// round 15
// baseline (speedup 1.0000x reference)
#include <cuda_runtime.h>
#include <cuda_fp16.h>
#include <mma.h>
#include <cstdint>

using namespace nvcuda;

// Scratch (__device__ globals; runtime alloc forbidden)
__device__ __half g_xa [13631488];  // [64 j1][1024 b][208 kpad]     fp16
__device__ __half g_k1h[13631488];  // [64 j1][208 kpad][1024 l1]    fp16 (native layout)
__device__ __half g_k3h[13631488];  // [64 j3][1024 k3][208 l3pad]   fp16 (native layout)
__device__ __half g_h2r[67108864];  // [64 j3][1024 b][1024 k3]      fp16
__device__ float  g_b2eff[65536];   // [4096 j2][16]  (b1@k2 + b2)

__device__ __forceinline__ uint32_t smem_u32(const void* p) {
    uint32_t a;
    asm("{ .reg .u64 t; cvta.to.shared.u64 t, %1; cvt.u32.u64 %0, t; }"
        : "=r"(a) : "l"(p));
    return a;
}
__device__ __forceinline__ uint32_t h2_u32(__half2 h) {
    return *reinterpret_cast<const uint32_t*>(&h);
}
__device__ __forceinline__ void cpa(uint32_t d, const void* s) {
    asm volatile("cp.async.cg.shared.global [%0], [%1], 16;" :: "r"(d), "l"(s));
}
__device__ __forceinline__ void cpcommit() { asm volatile("cp.async.commit_group;" ::: "memory"); }
__device__ __forceinline__ void cpwait0()  { asm volatile("cp.async.wait_group 0;" ::: "memory"); }
__device__ __forceinline__ void cpwait1()  { asm volatile("cp.async.wait_group 1;" ::: "memory"); }

// A tile [128 b][64 k]: stride 72 halves (144B) -> banks (36r)%32 distinct.
// B tile [64 k][128 n]: stride 136 halves (272B) -> banks (68r)%32 = 4r distinct.
#define LDM    72
#define ROWB   144
#define LDMB   136
#define ROWBB  272
#define A_OFF(b) ((b) * 18432)
#define B_OFF(b) (36864 + (b) * 18432)
#define SMEM_BYTES 73728
// g1f extras:
#define K2H_OFF   73728           // fp16 [8 rr][256]  (4096 B)
#define B2S_OFF   77824           // fp32 [8 rr][16]   (512 B)
#define G1F_SMEM  78336
// g1f epilogue overlays:
#define STG_LDM   136             // fp16 stage [128 cc][136] @0 (34816 B)
#define WSCR_OFF  36864           // fp32 warp scratch, 1KB/warp

#define KPAD 208

// ------------------------- fused prep kernel -------------------------------
// grid partition: [0,8192) gather_x | [8192,9024) k1 convert |
//                 [9024,13120) k3 convert | [13120,13632) biasprep
__global__ __launch_bounds__(256) void prep(
    const float* __restrict__ x,  const float* __restrict__ k1,
    const float* __restrict__ k3, const float* __restrict__ b1,
    const float* __restrict__ k2, const float* __restrict__ b2)
{
    const int blk = blockIdx.x, tid = threadIdx.x;
    const int lane = tid & 31, wrp = tid >> 5;

    if (blk < 8192) {
        // gather_x (float2 -> half2)
        const int b = blk >> 3;
        const int j1 = (blk & 7) * 8 + wrp;
        const int bx = j1 >> 3, by = j1 & 7;
        const float* xr = x + b * 12800;
        __half* dst = g_xa + (size_t)(j1 * 1024 + b) * KPAD;
#pragma unroll
        for (int it = 0; it < 4; it++) {
            int q = lane + it * 32;
            if (q < 104) {
                __half2 h;
                if (q < 100) {
                    int wx = q / 10, wy = q - wx * 10;
                    const float2 v = *reinterpret_cast<const float2*>(
                        xr + ((bx * 10 + wx) * 80 + by * 10 + wy) * 2);
                    h = __floats2half2_rn(v.x, v.y);
                } else {
                    h = __floats2half2_rn(0.0f, 0.0f);
                }
                *reinterpret_cast<__half2*>(dst + 2 * q) = h;
            }
        }
    } else if (blk < 9024) {
        // k1 convert: native layout [j1][k][l1], pad rows k 200..207 zero
        const int idx = blk - 8192;        // 0..831
        const int j1 = idx / 13, band = idx - j1 * 13;
        const int k0b = band * 16;
#pragma unroll
        for (int it = 0; it < 16; it++) {
            int pos = tid + it * 256;      // 0..4095 (16 rows x 256 float4)
            int row = pos >> 8, c4 = pos & 255;
            int k = k0b + row;
            uint2 out = make_uint2(0u, 0u);
            if (k < 200) {
                float4 v = *reinterpret_cast<const float4*>(
                    k1 + ((size_t)(j1 * 200 + k) << 10) + c4 * 4);
                out.x = h2_u32(__floats2half2_rn(v.x, v.y));
                out.y = h2_u32(__floats2half2_rn(v.z, v.w));
            }
            *reinterpret_cast<uint2*>(
                g_k1h + ((size_t)(j1 * 208 + k) << 10) + c4 * 4) = out;
        }
    } else if (blk < 13120) {
        // k3 convert: native layout [j3][k][l3 pad 208]
        const int idx = blk - 9024;        // 0..4095
        const int j3 = idx >> 6, band = idx & 63;
        const int k0b = band * 16;
#pragma unroll
        for (int it = 0; it < 4; it++) {
            int pos = tid + it * 256;      // 0..831 (16 rows x 52 chunks)
            if (pos < 832) {
                int row = pos / 52, c4 = pos - row * 52;
                int k = k0b + row;
                uint2 out = make_uint2(0u, 0u);
                if (c4 < 50) {
                    float4 v = *reinterpret_cast<const float4*>(
                        k3 + ((size_t)(j3 * 1024 + k)) * 200 + c4 * 4);
                    out.x = h2_u32(__floats2half2_rn(v.x, v.y));
                    out.y = h2_u32(__floats2half2_rn(v.z, v.w));
                }
                *reinterpret_cast<uint2*>(
                    g_k3h + ((size_t)(j3 * 1024 + k)) * 208 + c4 * 4) = out;
            }
        }
    } else {
        // biasprep: 8 j2 per block (one per warp), lanes 0..15 active
        const int j2 = (blk - 13120) * 8 + wrp;
        const int p = lane;
        if (p < 16) {
            const int r = j2 >> 8, j1 = (j2 >> 2) & 63, tt = j2 & 3;
            float s = b2[j2 * 16 + p];
#pragma unroll
            for (int k = 0; k < 16; k++)
                s += b1[j1 * 1024 + (tt * 16 + k) * 16 + r] * k2[j2 * 256 + k * 16 + p];
            g_b2eff[j2 * 16 + p] = s;
        }
    }
}

// ------------------------- compute one k-chunk -----------------------------
// A row-major [128 b][KW k] ldm=LDM; B row-major [KW k][128 n] ldm=LDMB.
template <int KW>
__device__ __forceinline__ void compute_chunk(
    const char* dsm, int buf, int wr, int wc, int jlim,
    wmma::fragment<wmma::accumulator, 16, 16, 16, float> (&acc)[2][4])
{
    const __half* As = (const __half*)(dsm + A_OFF(buf));
    const __half* Bs = (const __half*)(dsm + B_OFF(buf));
#pragma unroll
    for (int kk = 0; kk < KW; kk += 16) {
        wmma::fragment<wmma::matrix_a, 16, 16, 16, __half, wmma::row_major> af[2];
#pragma unroll
        for (int i = 0; i < 2; i++)
            wmma::load_matrix_sync(af[i], As + (wr * 32 + i * 16) * LDM + kk, LDM);
#pragma unroll
        for (int j = 0; j < 4; j++) {
            if (j < jlim) {
                wmma::fragment<wmma::matrix_b, 16, 16, 16, __half, wmma::row_major> bf;
                wmma::load_matrix_sync(bf, Bs + kk * LDMB + wc * 64 + j * 16, LDMB);
#pragma unroll
                for (int i = 0; i < 2; i++)
                    wmma::mma_sync(acc[i][j], af[i], bf, acc[i][j]);
            }
        }
    }
}

// ------------------------- GEMM1 fused with GEMM2 --------------------------
// CTA: 128 b-rows x 128 permuted l1-cols for (j1, t=bx>>1, rh=bx&1).
// Mainloop col cc' = p2lo*8 + rr  <->  l1 = (t*16 + p2lo)*16 + rh*8 + rr
// (8-contiguous l1 per 16B chunk). Phase A remaps cc' -> cc = rr*16 + p2lo.
__global__ __launch_bounds__(256, 2) void g1f(const float* __restrict__ k2) {
    extern __shared__ __align__(16) char dsm[];
    const int tid = threadIdx.x, wid = tid >> 5, lane = tid & 31;
    const int wr = wid >> 1, wc = wid & 1;
    const int bx = blockIdx.x, j1 = blockIdx.z, m0 = blockIdx.y * 128;
    const int t = bx >> 1, rh = bx & 1;
    const uint32_t sbase = smem_u32(dsm);

    // stage k2 (fp16) + b2eff for this CTA's 8 r values
    {
        __half* k2h = (__half*)(dsm + K2H_OFF);
        float*  b2s = (float*)(dsm + B2S_OFF);
        for (int i = tid; i < 2048; i += 256) {
            int rr = i >> 8, kp = i & 255;
            k2h[i] = __float2half_rn(
                k2[((rh * 8 + rr) * 256 + j1 * 4 + t) * 256 + kp]);
        }
        if (tid < 128) {
            int rr = tid >> 4, p = tid & 15;
            b2s[tid] = g_b2eff[(((rh * 8 + rr) * 256 + j1 * 4 + t) << 4) + p];
        }
    }

    const __half* aS = g_xa  + (size_t)(j1 * 1024 + m0) * KPAD;
    const __half* bS = g_k1h + ((size_t)(j1 * 208) << 10) + t * 256 + rh * 8;

    wmma::fragment<wmma::accumulator, 16, 16, 16, float> acc[2][4];
#pragma unroll
    for (int i = 0; i < 2; i++)
#pragma unroll
        for (int j = 0; j < 4; j++) wmma::fill_fragment(acc[i][j], 0.0f);

    // preload chunk 0: A 128 rows x 8 segs, B 64 k-rows x 16 chunks
    for (int i = tid; i < 1024; i += 256) {
        int ar = i >> 3, as = i & 7;
        cpa(sbase + A_OFF(0) + ar * ROWB + as * 16, aS + ar * KPAD + as * 8);
        int br = i >> 4, p2 = i & 15;
        cpa(sbase + B_OFF(0) + br * ROWBB + p2 * 16, bS + ((size_t)br << 10) + p2 * 16);
    }
    cpcommit();

    const int NC = 4;  // chunks: 64,64,64,16
    for (int c = 0; c < NC; c++) {
        const int buf = c & 1;
        if (c + 1 < NC) {
            const int nb = buf ^ 1, k0 = (c + 1) * 64;
            if (c + 1 < 3) {
                for (int i = tid; i < 1024; i += 256) {
                    int ar = i >> 3, as = i & 7;
                    cpa(sbase + A_OFF(nb) + ar * ROWB + as * 16,
                        aS + ar * KPAD + k0 + as * 8);
                    int br = i >> 4, p2 = i & 15;
                    cpa(sbase + B_OFF(nb) + br * ROWBB + p2 * 16,
                        bS + ((size_t)(k0 + br) << 10) + p2 * 16);
                }
            } else {  // tail: A 128x2 segs, B 16 rows x 16 chunks
                int ar = tid >> 1, as = tid & 1;
                cpa(sbase + A_OFF(nb) + ar * ROWB + as * 16,
                    aS + ar * KPAD + k0 + as * 8);
                int br = tid >> 4, p2 = tid & 15;
                if (br < 16)
                    cpa(sbase + B_OFF(nb) + br * ROWBB + p2 * 16,
                        bS + ((size_t)(k0 + br) << 10) + p2 * 16);
            }
            cpcommit();
            cpwait1();
        } else {
            cpwait0();
        }
        __syncthreads();
        if (c < 3) compute_chunk<64>(dsm, buf, wr, wc, 4, acc);
        else       compute_chunk<16>(dsm, buf, wr, wc, 4, acc);
        __syncthreads();
    }

    // ---- epilogue phase A: acc -> fp16 stage[cc][b], cc = rr*16 + p2lo ----
    __half* stage = (__half*)dsm;
    float* wscr = (float*)(dsm + WSCR_OFF + wid * 1024);
#pragma unroll
    for (int i = 0; i < 2; i++) {
#pragma unroll
        for (int j = 0; j < 4; j++) {
            wmma::store_matrix_sync(wscr, acc[i][j], 16, wmma::mem_col_major);
            __syncwarp();
            int cl = lane >> 1, boff = (lane & 1) * 8;
            float4 v0 = *(float4*)(wscr + cl * 16 + boff);
            float4 v1 = *(float4*)(wscr + cl * 16 + boff + 4);
            __half2 h0 = __floats2half2_rn(v0.x, v0.y);
            __half2 h1 = __floats2half2_rn(v0.z, v0.w);
            __half2 h2 = __floats2half2_rn(v1.x, v1.y);
            __half2 h3 = __floats2half2_rn(v1.z, v1.w);
            int ccp = wc * 64 + j * 16 + cl;                  // mainloop col
            int ccs = ((ccp & 7) << 4) + (ccp >> 3);          // rr*16 + p2lo
            int mg = wr * 32 + i * 16;
            uint4 pk;
            pk.x = h2_u32(h0); pk.y = h2_u32(h1);
            pk.z = h2_u32(h2); pk.w = h2_u32(h3);
            *(uint4*)(stage + ccs * STG_LDM + mg + boff) = pk;
            __syncwarp();
        }
    }
    __syncthreads();

    // ---- epilogue phase B: warp rr applies k2 (16x16) and stores h2r ----
    {
        const __half* k2h = (const __half*)(dsm + K2H_OFF);
        const float*  b2s = (const float*)(dsm + B2S_OFF);
        const int rr = wid, r = rh * 8 + rr;
        wmma::fragment<wmma::matrix_b, 16, 16, 16, __half, wmma::row_major> bfr;
        wmma::load_matrix_sync(bfr, k2h + rr * 256, 16);
        const int j3 = r * 4 + (j1 >> 4);
        const int k3b = (j1 & 15) * 64 + t * 16;
        float b2v[8];
        {
            int poff = (lane & 1) * 8;
#pragma unroll
            for (int q = 0; q < 8; q++) b2v[q] = b2s[rr * 16 + poff + q];
        }
#pragma unroll
        for (int mb = 0; mb < 8; mb++) {
            wmma::fragment<wmma::matrix_a, 16, 16, 16, __half, wmma::col_major> afr;
            wmma::load_matrix_sync(afr, stage + (rr * 16) * STG_LDM + mb * 16, STG_LDM);
            wmma::fragment<wmma::accumulator, 16, 16, 16, float> oc;
            wmma::fill_fragment(oc, 0.0f);
            wmma::mma_sync(oc, afr, bfr, oc);
            wmma::store_matrix_sync(wscr, oc, 16, wmma::mem_row_major);
            __syncwarp();
            int b = lane >> 1, poff = (lane & 1) * 8;
            float4 v0 = *(float4*)(wscr + b * 16 + poff);
            float4 v1 = *(float4*)(wscr + b * 16 + poff + 4);
            __half2 h0 = __floats2half2_rn(v0.x + b2v[0], v0.y + b2v[1]);
            __half2 h1 = __floats2half2_rn(v0.z + b2v[2], v0.w + b2v[3]);
            __half2 h2 = __floats2half2_rn(v1.x + b2v[4], v1.y + b2v[5]);
            __half2 h3 = __floats2half2_rn(v1.z + b2v[6], v1.w + b2v[7]);
            uint4 pk;
            pk.x = h2_u32(h0); pk.y = h2_u32(h1);
            pk.z = h2_u32(h2); pk.w = h2_u32(h3);
            *(uint4*)(g_h2r + ((size_t)j3 * 1024 + m0 + mb * 16 + b) * 1024 +
                      k3b + poff) = pk;
            __syncwarp();
        }
    }
}

// ------------------------- GEMM3 ------------------------------------------
// n-tile 0: 128 cols; n-tile 1: 80 cols computed (72 valid).
__global__ __launch_bounds__(256, 2) void g3(const float* __restrict__ b3,
                                             float* __restrict__ out) {
    extern __shared__ __align__(16) char dsm[];
    const int tid = threadIdx.x, wid = tid >> 5;
    const int wr = wid >> 1, wc = wid & 1;
    const int j3 = blockIdx.z, n0 = blockIdx.x * 128, m0 = blockIdx.y * 128;
    const uint32_t sbase = smem_u32(dsm);

    const int ncols = (n0 == 0) ? 128 : 80;
    const int segs = ncols >> 3;   // 16B chunks per B row
    int jl = ((ncols - wc * 64) + 15) >> 4;
    if (jl < 0) jl = 0; if (jl > 4) jl = 4;
    const int jlim = jl;

    const __half* aS = g_h2r + ((size_t)(j3 * 1024 + m0)) * 1024;
    const __half* bS = g_k3h + ((size_t)j3 << 10) * 208 + n0;

    wmma::fragment<wmma::accumulator, 16, 16, 16, float> acc[2][4];
#pragma unroll
    for (int i = 0; i < 2; i++)
#pragma unroll
        for (int j = 0; j < 4; j++) wmma::fill_fragment(acc[i][j], 0.0f);

    // preload chunk 0
    for (int i = tid; i < 1024; i += 256) {
        int ar = i >> 3, as = i & 7;
        cpa(sbase + A_OFF(0) + ar * ROWB + as * 16, aS + ar * 1024 + as * 8);
        int br = i >> 4, sg = i & 15;
        if (sg < segs)
            cpa(sbase + B_OFF(0) + br * ROWBB + sg * 16,
                bS + (size_t)br * 208 + sg * 8);
    }
    cpcommit();

    const int NC = 16;
    for (int c = 0; c < NC; c++) {
        const int buf = c & 1;
        if (c + 1 < NC) {
            const int nb = buf ^ 1, k0 = (c + 1) * 64;
            for (int i = tid; i < 1024; i += 256) {
                int ar = i >> 3, as = i & 7;
                cpa(sbase + A_OFF(nb) + ar * ROWB + as * 16,
                    aS + ar * 1024 + k0 + as * 8);
                int br = i >> 4, sg = i & 15;
                if (sg < segs)
                    cpa(sbase + B_OFF(nb) + br * ROWBB + sg * 16,
                        bS + (size_t)(k0 + br) * 208 + sg * 8);
            }
            cpcommit();
            cpwait1();
        } else {
            cpwait0();
        }
        __syncthreads();
        compute_chunk<64>(dsm, buf, wr, wc, jlim, acc);
        __syncthreads();
    }

    float* stage = (float*)dsm;
    const int b2x = j3 >> 3, b2y = j3 & 7;
#pragma unroll
    for (int h = 0; h < 2; ++h) {
        if (wc == h) {
#pragma unroll
            for (int i = 0; i < 2; i++)
#pragma unroll
                for (int j = 0; j < 4; j++)
                    wmma::store_matrix_sync(
                        stage + (wr * 32 + i * 16) * 68 + j * 16,
                        acc[i][j], 68, wmma::mem_row_major);
        }
        __syncthreads();
        for (int e = tid; e < 8192; e += 256) {
            int cc = e & 63, row = e >> 6;
            int l3 = n0 + h * 64 + cc;
            if (l3 < 200) {
                float v = stage[row * 68 + cc] + b3[j3 * 200 + l3];
                int q = l3 >> 1, c = l3 & 1;
                int w2x = q / 10, w2y = q - w2x * 10;
                out[(m0 + row) * 12800 +
                    ((b2x * 10 + w2x) * 80 + b2y * 10 + w2y) * 2 + c] = v;
            }
        }
        __syncthreads();
    }
}

extern "C" void kernel_launch(void* const* d_in, const int* in_sizes, int n_in,
                              void* d_out, int out_size) {
    const float* x   = (const float*)d_in[0];
    const float* k1  = (const float*)d_in[1];
    const float* b1  = (const float*)d_in[2];
    const float* k2  = (const float*)d_in[3];
    const float* b2  = (const float*)d_in[4];
    const float* k3w = (const float*)d_in[5];
    const float* b3  = (const float*)d_in[6];
    float* out = (float*)d_out;

    cudaFuncSetAttribute(g1f, cudaFuncAttributeMaxDynamicSharedMemorySize, G1F_SMEM);
    cudaFuncSetAttribute(g3,  cudaFuncAttributeMaxDynamicSharedMemorySize, SMEM_BYTES);

    prep<<<13632, 256>>>(x, k1, k3w, b1, k2, b2);
    g1f<<<dim3(8, 8, 64), 256, G1F_SMEM>>>(k2);
    g3 <<<dim3(2, 8, 64), 256, SMEM_BYTES>>>(b3, out);
}

// round 17
// speedup vs baseline: 1.0405x; 1.0405x over previous
#include <cuda_runtime.h>
#include <cuda_fp16.h>
#include <mma.h>
#include <cstdint>

using namespace nvcuda;

// Scratch (__device__ globals; runtime alloc forbidden)
__device__ __half g_xa [13631488];  // [64 j1][1024 b][208 kpad]   fp16
__device__ __half g_k1t[13631488];  // [64 j1][1024 l1][208 kpad]  fp16
__device__ __half g_k3t[16777216];  // [64 j3][256 l3pad][1024 k3] fp16
__device__ __half g_h2r[67108864];  // [64 j3][1024 b][1024 k3]    fp16
__device__ float  g_b2eff[65536];   // [4096 j2][16]  (b1@k2 + b2)

__device__ __forceinline__ uint32_t smem_u32(const void* p) {
    uint32_t a;
    asm("{ .reg .u64 t; cvta.to.shared.u64 t, %1; cvt.u32.u64 %0, t; }"
        : "=r"(a) : "l"(p));
    return a;
}
__device__ __forceinline__ uint32_t h2_u32(__half2 h) {
    return *reinterpret_cast<const uint32_t*>(&h);
}
__device__ __forceinline__ void cpa(uint32_t d, const void* s) {
    asm volatile("cp.async.cg.shared.global [%0], [%1], 16;" :: "r"(d), "l"(s));
}
__device__ __forceinline__ void cpcommit() { asm volatile("cp.async.commit_group;" ::: "memory"); }
__device__ __forceinline__ void cpwait0()  { asm volatile("cp.async.wait_group 0;" ::: "memory"); }
__device__ __forceinline__ void cpwait1()  { asm volatile("cp.async.wait_group 1;" ::: "memory"); }

// k-chunk 64. Row stride 72 halves (144B): LDSM banks (36*r)%32 all distinct
// per 8-row phase => conflict-free (validated R10/R11/R13).
#define LDM   72
#define ROWB  144
#define A_OFF(b) ((b) * 18432)
#define B_OFF(b) (36864 + (b) * 18432)
#define SMEM_BYTES 73728
// g1f extras:
#define K2H_OFF   73728           // fp16 [8 rr][256]  (4096 B)
#define B2S_OFF   77824           // fp32 [8 rr][16]   (512 B)
#define G1F_SMEM  78336
// g1f epilogue overlays:
#define STG_LDM   136             // fp16 stage [128 cc][136] @0 (34816 B)
#define WSCR_OFF  36864           // fp32 warp scratch, 1KB/warp

#define KPAD 208

// ------------------------- fused prep kernel -------------------------------
// grid partition: [0,8192) gather_x | [8192,22528) k1 transpose |
//                 [22528,36864) k3 transpose | [36864,37376) biasprep
__global__ __launch_bounds__(256) void prep(
    const float* __restrict__ x,  const float* __restrict__ k1,
    const float* __restrict__ k3, const float* __restrict__ b1,
    const float* __restrict__ k2, const float* __restrict__ b2)
{
    __shared__ float t[32][33];
    const int blk = blockIdx.x, tid = threadIdx.x;
    const int lane = tid & 31, wrp = tid >> 5;

    if (blk < 8192) {
        // gather_x (float2 -> half2)
        const int b = blk >> 3;
        const int j1 = (blk & 7) * 8 + wrp;
        const int bx = j1 >> 3, by = j1 & 7;
        const float* xr = x + b * 12800;
        __half* dst = g_xa + (size_t)(j1 * 1024 + b) * KPAD;
#pragma unroll
        for (int it = 0; it < 4; it++) {
            int q = lane + it * 32;
            if (q < 104) {
                __half2 h;
                if (q < 100) {
                    int wx = q / 10, wy = q - wx * 10;
                    const float2 v = *reinterpret_cast<const float2*>(
                        xr + ((bx * 10 + wx) * 80 + by * 10 + wy) * 2);
                    h = __floats2half2_rn(v.x, v.y);
                } else {
                    h = __floats2half2_rn(0.0f, 0.0f);
                }
                *reinterpret_cast<__half2*>(dst + 2 * q) = h;
            }
        }
    } else if (blk < 22528) {
        // k1 transpose -> g_k1t [j1][l1][KPAD], half2 stores along k
        const int idx = blk - 8192;            // 0..14335
        const int j1 = idx / 224, rem = idx - j1 * 224;
        const int l0 = (rem & 31) * 32;
        const int k0 = (rem >> 5) * 32;        // 7 bands: 0..192
        const int tx = lane, ty = wrp;
#pragma unroll
        for (int r = 0; r < 32; r += 8) {
            int k = k0 + ty + r;
            t[ty + r][tx] = (k < 200) ? k1[((size_t)(j1 * 200 + k) << 10) + l0 + tx] : 0.0f;
        }
        __syncthreads();
#pragma unroll
        for (int it = 0; it < 2; it++) {
            int e = tid + it * 256;            // 0..511
            int lr = e >> 4, kk = e & 15;
            int k = k0 + 2 * kk;
            if (k < KPAD) {
                __half2 h = __floats2half2_rn(t[2 * kk][lr], t[2 * kk + 1][lr]);
                *reinterpret_cast<__half2*>(
                    g_k1t + (size_t)(j1 * 1024 + l0 + lr) * KPAD + k) = h;
            }
        }
    } else if (blk < 36864) {
        // k3 transpose -> g_k3t [j3][l3 256][1024], half2 stores along k
        const int idx = blk - 22528;           // 0..14335
        const int j3 = idx / 224, rem = idx - j3 * 224;
        const int k0 = (rem & 31) * 32;        // 32 k-bands
        const int l0 = (rem >> 5) * 32;        // 7 l-bands: 0..192 (224 rows)
        const int tx = lane, ty = wrp;
#pragma unroll
        for (int r = 0; r < 32; r += 8) {
            int l = l0 + tx, k = k0 + ty + r;
            t[ty + r][tx] = (l < 200) ? k3[(size_t)(j3 * 1024 + k) * 200 + l] : 0.0f;
        }
        __syncthreads();
#pragma unroll
        for (int it = 0; it < 2; it++) {
            int e = tid + it * 256;
            int lr = e >> 4, kk = e & 15;
            int l = l0 + lr;
            if (l < 208) {
                __half2 h = __floats2half2_rn(t[2 * kk][lr], t[2 * kk + 1][lr]);
                *reinterpret_cast<__half2*>(
                    g_k3t + ((size_t)(j3 * 256 + l) << 10) + k0 + 2 * kk) = h;
            }
        }
    } else {
        // biasprep: 8 j2 per block (one per warp), lanes 0..15 active
        const int j2 = (blk - 36864) * 8 + wrp;
        const int p = lane;
        if (p < 16) {
            const int r = j2 >> 8, j1 = (j2 >> 2) & 63, tt = j2 & 3;
            float s = b2[j2 * 16 + p];
#pragma unroll
            for (int k = 0; k < 16; k++)
                s += b1[j1 * 1024 + (tt * 16 + k) * 16 + r] * k2[j2 * 256 + k * 16 + p];
            g_b2eff[j2 * 16 + p] = s;
        }
    }
}

// ------------------------- compute one k-chunk -----------------------------
template <int KW>
__device__ __forceinline__ void compute_chunk(
    const char* dsm, int buf, int wr, int wc, int jlim,
    wmma::fragment<wmma::accumulator, 16, 16, 16, float> (&acc)[2][4])
{
    const __half* As = (const __half*)(dsm + A_OFF(buf));
    const __half* Bs = (const __half*)(dsm + B_OFF(buf));
#pragma unroll
    for (int kk = 0; kk < KW; kk += 16) {
        wmma::fragment<wmma::matrix_a, 16, 16, 16, __half, wmma::row_major> af[2];
#pragma unroll
        for (int i = 0; i < 2; i++)
            wmma::load_matrix_sync(af[i], As + (wr * 32 + i * 16) * LDM + kk, LDM);
#pragma unroll
        for (int j = 0; j < 4; j++) {
            if (j < jlim) {
                wmma::fragment<wmma::matrix_b, 16, 16, 16, __half, wmma::col_major> bf;
                wmma::load_matrix_sync(bf, Bs + (wc * 64 + j * 16) * LDM + kk, LDM);
#pragma unroll
                for (int i = 0; i < 2; i++)
                    wmma::mma_sync(acc[i][j], af[i], bf, acc[i][j]);
            }
        }
    }
}

// ------------------------- GEMM1 fused with GEMM2 --------------------------
// CTA: 128 b-rows x 128 permuted l1-cols for (j1, t=bx>>1, rh=bx&1).
// col cc = rr*16 + p2lo  ->  l1 = (t*16 + p2lo)*16 + rh*8 + rr
// K = 208 (3 full 64-chunks + one 16-wide tail chunk).
__global__ __launch_bounds__(256, 2) void g1f(const float* __restrict__ k2) {
    extern __shared__ __align__(16) char dsm[];
    const int tid = threadIdx.x, wid = tid >> 5, lane = tid & 31;
    const int wr = wid >> 1, wc = wid & 1;
    const int bx = blockIdx.x, j1 = blockIdx.z, m0 = blockIdx.y * 128;
    const int t = bx >> 1, rh = bx & 1;
    const uint32_t sbase = smem_u32(dsm);

    // stage k2 (fp16) + b2eff for this CTA's 8 r values
    {
        __half* k2h = (__half*)(dsm + K2H_OFF);
        float*  b2s = (float*)(dsm + B2S_OFF);
        for (int i = tid; i < 2048; i += 256) {
            int rr = i >> 8, kp = i & 255;
            k2h[i] = __float2half_rn(
                k2[((rh * 8 + rr) * 256 + j1 * 4 + t) * 256 + kp]);
        }
        if (tid < 128) {
            int rr = tid >> 4, p = tid & 15;
            b2s[tid] = g_b2eff[(((rh * 8 + rr) * 256 + j1 * 4 + t) << 4) + p];
        }
    }

    const __half* aS = g_xa  + (size_t)(j1 * 1024 + m0) * KPAD;
    const __half* bS = g_k1t + (size_t)j1 * 1024 * KPAD;

    wmma::fragment<wmma::accumulator, 16, 16, 16, float> acc[2][4];
#pragma unroll
    for (int i = 0; i < 2; i++)
#pragma unroll
        for (int j = 0; j < 4; j++) wmma::fill_fragment(acc[i][j], 0.0f);

    // preload chunk 0 (full)
    for (int i = tid; i < 1024; i += 256) {
        int row = i >> 3, seg = i & 7;
        int l1 = ((t * 16 + (row & 15)) << 4) + rh * 8 + (row >> 4);
        cpa(sbase + A_OFF(0) + row * ROWB + seg * 16, aS + row * KPAD + seg * 8);
        cpa(sbase + B_OFF(0) + row * ROWB + seg * 16, bS + l1 * KPAD + seg * 8);
    }
    cpcommit();

    const int NC = 4;  // chunks: 64,64,64,16
    for (int c = 0; c < NC; c++) {
        const int buf = c & 1;
        if (c + 1 < NC) {
            const int nb = buf ^ 1, k0 = (c + 1) * 64;
            if (c + 1 < 3) {
                for (int i = tid; i < 1024; i += 256) {
                    int row = i >> 3, seg = i & 7;
                    int l1 = ((t * 16 + (row & 15)) << 4) + rh * 8 + (row >> 4);
                    cpa(sbase + A_OFF(nb) + row * ROWB + seg * 16,
                        aS + row * KPAD + k0 + seg * 8);
                    cpa(sbase + B_OFF(nb) + row * ROWB + seg * 16,
                        bS + l1 * KPAD + k0 + seg * 8);
                }
            } else {  // tail: 16 halves = 2 segs
                int row = tid >> 1, seg = tid & 1;
                int l1 = ((t * 16 + (row & 15)) << 4) + rh * 8 + (row >> 4);
                cpa(sbase + A_OFF(nb) + row * ROWB + seg * 16,
                    aS + row * KPAD + k0 + seg * 8);
                cpa(sbase + B_OFF(nb) + row * ROWB + seg * 16,
                    bS + l1 * KPAD + k0 + seg * 8);
            }
            cpcommit();
            cpwait1();
        } else {
            cpwait0();
        }
        __syncthreads();
        if (c < 3) compute_chunk<64>(dsm, buf, wr, wc, 4, acc);
        else       compute_chunk<16>(dsm, buf, wr, wc, 4, acc);
        __syncthreads();
    }

    // ---- epilogue phase A: acc -> fp16 stage[cc][b] ----
    __half* stage = (__half*)dsm;
    float* wscr = (float*)(dsm + WSCR_OFF + wid * 1024);
#pragma unroll
    for (int i = 0; i < 2; i++) {
#pragma unroll
        for (int j = 0; j < 4; j++) {
            wmma::store_matrix_sync(wscr, acc[i][j], 16, wmma::mem_col_major);
            __syncwarp();
            int cl = lane >> 1, boff = (lane & 1) * 8;
            float4 v0 = *(float4*)(wscr + cl * 16 + boff);
            float4 v1 = *(float4*)(wscr + cl * 16 + boff + 4);
            __half2 h0 = __floats2half2_rn(v0.x, v0.y);
            __half2 h1 = __floats2half2_rn(v0.z, v0.w);
            __half2 h2 = __floats2half2_rn(v1.x, v1.y);
            __half2 h3 = __floats2half2_rn(v1.z, v1.w);
            int ccg = wc * 64 + j * 16 + cl, mg = wr * 32 + i * 16;
            uint4 pk;
            pk.x = h2_u32(h0); pk.y = h2_u32(h1);
            pk.z = h2_u32(h2); pk.w = h2_u32(h3);
            *(uint4*)(stage + ccg * STG_LDM + mg + boff) = pk;
            __syncwarp();
        }
    }
    __syncthreads();

    // ---- epilogue phase B: warp rr applies k2 (16x16) and stores h2r ----
    {
        const __half* k2h = (const __half*)(dsm + K2H_OFF);
        const float*  b2s = (const float*)(dsm + B2S_OFF);
        const int rr = wid, r = rh * 8 + rr;
        wmma::fragment<wmma::matrix_b, 16, 16, 16, __half, wmma::row_major> bfr;
        wmma::load_matrix_sync(bfr, k2h + rr * 256, 16);
        const int j3 = r * 4 + (j1 >> 4);
        const int k3b = (j1 & 15) * 64 + t * 16;
        float b2v[8];
        {
            int poff = (lane & 1) * 8;
#pragma unroll
            for (int q = 0; q < 8; q++) b2v[q] = b2s[rr * 16 + poff + q];
        }
#pragma unroll
        for (int mb = 0; mb < 8; mb++) {
            wmma::fragment<wmma::matrix_a, 16, 16, 16, __half, wmma::col_major> afr;
            wmma::load_matrix_sync(afr, stage + (rr * 16) * STG_LDM + mb * 16, STG_LDM);
            wmma::fragment<wmma::accumulator, 16, 16, 16, float> oc;
            wmma::fill_fragment(oc, 0.0f);
            wmma::mma_sync(oc, afr, bfr, oc);
            wmma::store_matrix_sync(wscr, oc, 16, wmma::mem_row_major);
            __syncwarp();
            int b = lane >> 1, poff = (lane & 1) * 8;
            float4 v0 = *(float4*)(wscr + b * 16 + poff);
            float4 v1 = *(float4*)(wscr + b * 16 + poff + 4);
            __half2 h0 = __floats2half2_rn(v0.x + b2v[0], v0.y + b2v[1]);
            __half2 h1 = __floats2half2_rn(v0.z + b2v[2], v0.w + b2v[3]);
            __half2 h2 = __floats2half2_rn(v1.x + b2v[4], v1.y + b2v[5]);
            __half2 h3 = __floats2half2_rn(v1.z + b2v[6], v1.w + b2v[7]);
            uint4 pk;
            pk.x = h2_u32(h0); pk.y = h2_u32(h1);
            pk.z = h2_u32(h2); pk.w = h2_u32(h3);
            *(uint4*)(g_h2r + ((size_t)j3 * 1024 + m0 + mb * 16 + b) * 1024 +
                      k3b + poff) = pk;
            __syncwarp();
        }
    }
}

// ------------------------- GEMM3 ------------------------------------------
// n-tile 0: 128 cols; n-tile 1: 80 cols computed (72 valid).
__global__ __launch_bounds__(256, 2) void g3(const float* __restrict__ b3,
                                             float* __restrict__ out) {
    extern __shared__ __align__(16) char dsm[];
    const int tid = threadIdx.x, wid = tid >> 5;
    const int wr = wid >> 1, wc = wid & 1;
    const int j3 = blockIdx.z, n0 = blockIdx.x * 128, m0 = blockIdx.y * 128;
    const uint32_t sbase = smem_u32(dsm);

    const int ncols = (n0 == 0) ? 128 : 80;
    int jl = ((ncols - wc * 64) + 15) >> 4;
    if (jl < 0) jl = 0; if (jl > 4) jl = 4;
    const int jlim = jl;
    const int bload = ncols * 8;   // rows*8 segs

    const __half* aS = g_h2r + ((size_t)(j3 * 1024 + m0)) * 1024;
    const __half* bS = g_k3t + (((size_t)(j3 * 256 + n0)) << 10);

    wmma::fragment<wmma::accumulator, 16, 16, 16, float> acc[2][4];
#pragma unroll
    for (int i = 0; i < 2; i++)
#pragma unroll
        for (int j = 0; j < 4; j++) wmma::fill_fragment(acc[i][j], 0.0f);

    // preload chunk 0
    for (int i = tid; i < 1024; i += 256) {
        int row = i >> 3, seg = i & 7;
        cpa(sbase + A_OFF(0) + row * ROWB + seg * 16, aS + row * 1024 + seg * 8);
        if (i < bload)
            cpa(sbase + B_OFF(0) + row * ROWB + seg * 16,
                bS + ((size_t)row << 10) + seg * 8);
    }
    cpcommit();

    const int NC = 16;
    for (int c = 0; c < NC; c++) {
        const int buf = c & 1;
        if (c + 1 < NC) {
            const int nb = buf ^ 1, k0 = (c + 1) * 64;
            for (int i = tid; i < 1024; i += 256) {
                int row = i >> 3, seg = i & 7;
                cpa(sbase + A_OFF(nb) + row * ROWB + seg * 16,
                    aS + row * 1024 + k0 + seg * 8);
                if (i < bload)
                    cpa(sbase + B_OFF(nb) + row * ROWB + seg * 16,
                        bS + ((size_t)row << 10) + k0 + seg * 8);
            }
            cpcommit();
            cpwait1();
        } else {
            cpwait0();
        }
        __syncthreads();
        compute_chunk<64>(dsm, buf, wr, wc, jlim, acc);
        __syncthreads();
    }

    float* stage = (float*)dsm;
    const int b2x = j3 >> 3, b2y = j3 & 7;
#pragma unroll
    for (int h = 0; h < 2; ++h) {
        if (wc == h) {
#pragma unroll
            for (int i = 0; i < 2; i++)
#pragma unroll
                for (int j = 0; j < 4; j++)
                    wmma::store_matrix_sync(
                        stage + (wr * 32 + i * 16) * 68 + j * 16,
                        acc[i][j], 68, wmma::mem_row_major);
        }
        __syncthreads();
        for (int e = tid; e < 8192; e += 256) {
            int cc = e & 63, row = e >> 6;
            int l3 = n0 + h * 64 + cc;
            if (l3 < 200) {
                float v = stage[row * 68 + cc] + b3[j3 * 200 + l3];
                int q = l3 >> 1, c = l3 & 1;
                int w2x = q / 10, w2y = q - w2x * 10;
                out[(m0 + row) * 12800 +
                    ((b2x * 10 + w2x) * 80 + b2y * 10 + w2y) * 2 + c] = v;
            }
        }
        __syncthreads();
    }
}

extern "C" void kernel_launch(void* const* d_in, const int* in_sizes, int n_in,
                              void* d_out, int out_size) {
    const float* x   = (const float*)d_in[0];
    const float* k1  = (const float*)d_in[1];
    const float* b1  = (const float*)d_in[2];
    const float* k2  = (const float*)d_in[3];
    const float* b2  = (const float*)d_in[4];
    const float* k3w = (const float*)d_in[5];
    const float* b3  = (const float*)d_in[6];
    float* out = (float*)d_out;

    cudaFuncSetAttribute(g1f, cudaFuncAttributeMaxDynamicSharedMemorySize, G1F_SMEM);
    cudaFuncSetAttribute(g3,  cudaFuncAttributeMaxDynamicSharedMemorySize, SMEM_BYTES);

    prep<<<37376, 256>>>(x, k1, k3w, b1, k2, b2);
    g1f<<<dim3(8, 8, 64), 256, G1F_SMEM>>>(k2);
    g3 <<<dim3(2, 8, 64), 256, SMEM_BYTES>>>(b3, out);
}